// round 2
// baseline (speedup 1.0000x reference)
#include <cuda_runtime.h>
#include <cstdint>

#define N_NODES  50000
#define N_EDGES  400000
#define N_GRAPHS 64

// ---------------- scratch (device globals; no allocation allowed) ----------
__device__ float g_y1[N_NODES * 256];   // [x@W1l | x@W1r]
__device__ float g_agg1[N_NODES * 128]; // segment sum of y1l over edges
__device__ float g_cnt[N_NODES];        // in-degree (float)
__device__ float g_h1[N_NODES * 128];   // relu(layer1)
__device__ float g_y2[N_NODES * 64];    // [h1@W2l | h1@W2r]
__device__ float g_agg2[N_NODES * 32];
__device__ float g_gsum[N_GRAPHS * 32];
__device__ float g_gcnt[N_GRAPHS];

// ---------------- zero scratch accumulators --------------------------------
__global__ void zero_kernel() {
    size_t i = (size_t)blockIdx.x * blockDim.x + threadIdx.x;
    size_t stride = (size_t)gridDim.x * blockDim.x;
    for (size_t k = i; k < (size_t)N_NODES * 128; k += stride) g_agg1[k] = 0.f;
    for (size_t k = i; k < (size_t)N_NODES * 32;  k += stride) g_agg2[k] = 0.f;
    for (size_t k = i; k < (size_t)N_NODES;       k += stride) g_cnt[k]  = 0.f;
    for (size_t k = i; k < (size_t)N_GRAPHS * 32; k += stride) g_gsum[k] = 0.f;
    for (size_t k = i; k < (size_t)N_GRAPHS;      k += stride) g_gcnt[k] = 0.f;
}

// ---------------- generic fp32 GEMM, C = A @ [Wl | Wr] ---------------------
// A: [M, K] row-major.  Wl, Wr: [K, HALFN] row-major.  C: [M, 2*HALFN].
template<int BM, int BN, int BK, int TM, int TN, int HALFN>
__launch_bounds__(256)
__global__ void sgemm_dualw(const float* __restrict__ A,
                            const float* __restrict__ Wl,
                            const float* __restrict__ Wr,
                            float* __restrict__ C, int M, int K)
{
    constexpr int N = 2 * HALFN;
    __shared__ float As[BK][BM];
    __shared__ float Bs[BK][BN];

    const int tid = threadIdx.x;
    const int rowBase = blockIdx.y * BM;
    const int colBase = blockIdx.x * BN;

    constexpr int TX = BN / TN;        // threads along N
    const int tx = tid % TX;
    const int ty = tid / TX;

    float acc[TM][TN];
#pragma unroll
    for (int i = 0; i < TM; i++)
#pragma unroll
        for (int j = 0; j < TN; j++) acc[i][j] = 0.f;

    // A-load mapping: float4 along K
    constexpr int AKT = BK / 4;
    constexpr int AROWS = 256 / AKT;
    constexpr int APASS = BM / AROWS;
    const int aRow = tid / AKT;
    const int aK4  = (tid % AKT) * 4;

    // B-load mapping: float4 along N
    constexpr int BNT = BN / 4;
    constexpr int BKP = 256 / BNT;
    constexpr int BPASS = BK / BKP;
    const int bK  = tid / BNT;
    const int bN4 = (tid % BNT) * 4;

    for (int kt = 0; kt < K; kt += BK) {
#pragma unroll
        for (int p = 0; p < APASS; p++) {
            int r = aRow + p * AROWS;
            int gr = rowBase + r;
            float4 v = make_float4(0.f, 0.f, 0.f, 0.f);
            if (gr < M) v = *(const float4*)(A + (size_t)gr * K + kt + aK4);
            As[aK4 + 0][r] = v.x; As[aK4 + 1][r] = v.y;
            As[aK4 + 2][r] = v.z; As[aK4 + 3][r] = v.w;
        }
#pragma unroll
        for (int p = 0; p < BPASS; p++) {
            int k = bK + p * BKP;
            int gn = colBase + bN4;
            const float* src = (gn < HALFN)
                ? (Wl + (size_t)(kt + k) * HALFN + gn)
                : (Wr + (size_t)(kt + k) * HALFN + (gn - HALFN));
            *(float4*)&Bs[k][bN4] = *(const float4*)src;
        }
        __syncthreads();

#pragma unroll
        for (int kk = 0; kk < BK; kk++) {
            float a[TM], b[TN];
#pragma unroll
            for (int i = 0; i < TM; i++) a[i] = As[kk][ty * TM + i];
#pragma unroll
            for (int j = 0; j < TN; j++) b[j] = Bs[kk][tx * TN + j];
#pragma unroll
            for (int i = 0; i < TM; i++)
#pragma unroll
                for (int j = 0; j < TN; j++)
                    acc[i][j] = fmaf(a[i], b[j], acc[i][j]);
        }
        __syncthreads();
    }

#pragma unroll
    for (int i = 0; i < TM; i++) {
        int gr = rowBase + ty * TM + i;
        if (gr < M) {
#pragma unroll
            for (int j = 0; j < TN; j += 4) {
                float4 v = make_float4(acc[i][j], acc[i][j + 1], acc[i][j + 2], acc[i][j + 3]);
                *(float4*)(C + (size_t)gr * N + colBase + tx * TN + j) = v;
            }
        }
    }
}

// ---------------- edge aggregation, layer 1 (128 feats, warp per edge) -----
__global__ void edge_agg1(const int* __restrict__ ei) {
    int gtid = blockIdx.x * blockDim.x + threadIdx.x;
    int e = gtid >> 5;
    int lane = gtid & 31;
    if (e >= N_EDGES) return;
    int src = ei[e];
    int dst = ei[N_EDGES + e];
    float4 v = *(const float4*)(g_y1 + (size_t)src * 256 + lane * 4);
    float* p = g_agg1 + (size_t)dst * 128 + lane * 4;
    asm volatile("red.global.add.v4.f32 [%0], {%1,%2,%3,%4};"
                 :: "l"(p), "f"(v.x), "f"(v.y), "f"(v.z), "f"(v.w) : "memory");
    if (lane == 0) atomicAdd(&g_cnt[dst], 1.0f);
}

// ---------------- layer-1 epilogue: h1 = relu(agg/cnt + b1l + y1r) ---------
__global__ void epi1(const float* __restrict__ b1l) {
    int m = blockIdx.x;
    int f = threadIdx.x;           // 128
    float inv = 1.0f / fmaxf(g_cnt[m], 1.0f);
    float v = g_agg1[(size_t)m * 128 + f] * inv + b1l[f] + g_y1[(size_t)m * 256 + 128 + f];
    g_h1[(size_t)m * 128 + f] = fmaxf(v, 0.f);
}

// ---------------- edge aggregation, layer 2 (32 feats, 8 threads/edge) -----
__global__ void edge_agg2(const int* __restrict__ ei) {
    int gtid = blockIdx.x * blockDim.x + threadIdx.x;
    int e = gtid >> 3;
    int lane = gtid & 7;
    if (e >= N_EDGES) return;
    int src = ei[e];
    int dst = ei[N_EDGES + e];
    float4 v = *(const float4*)(g_y2 + (size_t)src * 64 + lane * 4);
    float* p = g_agg2 + (size_t)dst * 32 + lane * 4;
    asm volatile("red.global.add.v4.f32 [%0], {%1,%2,%3,%4};"
                 :: "l"(p), "f"(v.x), "f"(v.y), "f"(v.z), "f"(v.w) : "memory");
}

// ---------------- fused layer-2 epilogue + per-graph mean pool --------------
// batch is sorted, so each thread register-accumulates and flushes on graph
// change (few atomics total).
__global__ void pool_kernel(const int* __restrict__ batch, const float* __restrict__ b2l) {
    int f = threadIdx.x;           // 32
    int yid = threadIdx.y;         // 8
    int n0 = blockIdx.x * 512 + yid;
    float b = b2l[f];
    float acc = 0.f, cacc = 0.f;
    int cur = -1;
    for (int it = 0; it < 64; it++) {
        int n = n0 + it * 8;
        if (n < N_NODES) {
            int g = batch[n];
            if (g != cur) {
                if (cur >= 0) {
                    atomicAdd(&g_gsum[cur * 32 + f], acc);
                    if (f == 0) atomicAdd(&g_gcnt[cur], cacc);
                }
                cur = g; acc = 0.f; cacc = 0.f;
            }
            float inv = 1.0f / fmaxf(g_cnt[n], 1.0f);
            float v = g_agg2[(size_t)n * 32 + f] * inv + b + g_y2[(size_t)n * 64 + 32 + f];
            acc += fmaxf(v, 0.f);
            cacc += 1.f;
        }
    }
    if (cur >= 0) {
        atomicAdd(&g_gsum[cur * 32 + f], acc);
        if (f == 0) atomicAdd(&g_gcnt[cur], cacc);
    }
}

// ---------------- final tiny MLP (encoder head + decoder) ------------------
__global__ void mlp_kernel(const float* __restrict__ Wl1, const float* __restrict__ bl1,
                           const float* __restrict__ Wl2, const float* __restrict__ bl2,
                           const float* __restrict__ Wd1, const float* __restrict__ bd1,
                           const float* __restrict__ Wd2, const float* __restrict__ bd2,
                           const float* __restrict__ Wd3, const float* __restrict__ bd3,
                           float* __restrict__ out) {
    __shared__ float sWl1[1024], sWl2[512], sWd1[512], sWd2[1024], sWd3[1600];
    __shared__ float sbl1[32], sbl2[16], sbd1[32], sbd2[32], sbd3[50];
    int t = threadIdx.x;           // 64
    for (int i = t; i < 1024; i += 64) sWl1[i] = Wl1[i];
    for (int i = t; i < 512;  i += 64) sWl2[i] = Wl2[i];
    for (int i = t; i < 512;  i += 64) sWd1[i] = Wd1[i];
    for (int i = t; i < 1024; i += 64) sWd2[i] = Wd2[i];
    for (int i = t; i < 1600; i += 64) sWd3[i] = Wd3[i];
    if (t < 32) sbl1[t] = bl1[t];
    if (t < 16) sbl2[t] = bl2[t];
    if (t < 32) sbd1[t] = bd1[t];
    if (t < 32) sbd2[t] = bd2[t];
    for (int i = t; i < 50; i += 64) sbd3[i] = bd3[i];
    __syncthreads();
    if (t >= N_GRAPHS) return;

    float gv[32];
    float inv = 1.0f / fmaxf(g_gcnt[t], 1.0f);
#pragma unroll
    for (int i = 0; i < 32; i++) gv[i] = g_gsum[t * 32 + i] * inv;

    float a[32];
#pragma unroll
    for (int j = 0; j < 32; j++) {
        float s = sbl1[j];
#pragma unroll
        for (int i = 0; i < 32; i++) s = fmaf(gv[i], sWl1[i * 32 + j], s);
        a[j] = fmaxf(s, 0.f);
    }
    float enc[16];
#pragma unroll
    for (int j = 0; j < 16; j++) {
        float s = sbl2[j];
#pragma unroll
        for (int i = 0; i < 32; i++) s = fmaf(a[i], sWl2[i * 16 + j], s);
        enc[j] = s > 0.f ? s : 0.1f * s;
    }
#pragma unroll
    for (int j = 0; j < 16; j++) out[t * 16 + j] = enc[j];

    float z1[32];
#pragma unroll
    for (int j = 0; j < 32; j++) {
        float s = sbd1[j];
#pragma unroll
        for (int i = 0; i < 16; i++) s = fmaf(enc[i], sWd1[i * 32 + j], s);
        z1[j] = s > 0.f ? s : 0.1f * s;
    }
    float z2[32];
#pragma unroll
    for (int j = 0; j < 32; j++) {
        float s = sbd2[j];
#pragma unroll
        for (int i = 0; i < 32; i++) s = fmaf(z1[i], sWd2[i * 32 + j], s);
        z2[j] = s > 0.f ? s : 0.1f * s;
    }
#pragma unroll
    for (int j = 0; j < 50; j++) {
        float s = sbd3[j];
#pragma unroll
        for (int i = 0; i < 32; i++) s = fmaf(z2[i], sWd3[i * 50 + j], s);  // FIXED: stride 50
        out[1024 + t * 50 + j] = s;
    }
}

// ---------------- launch ----------------------------------------------------
extern "C" void kernel_launch(void* const* d_in, const int* in_sizes, int n_in,
                              void* d_out, int out_size) {
    const float* x   = (const float*)d_in[0];
    const int*   ei  = (const int*)d_in[1];
    const int*   bat = (const int*)d_in[2];
    const float* W1l = (const float*)d_in[3];
    const float* b1l = (const float*)d_in[4];
    const float* W1r = (const float*)d_in[5];
    const float* W2l = (const float*)d_in[6];
    const float* b2l = (const float*)d_in[7];
    const float* W2r = (const float*)d_in[8];
    const float* Wl1 = (const float*)d_in[9];
    const float* bl1 = (const float*)d_in[10];
    const float* Wl2 = (const float*)d_in[11];
    const float* bl2 = (const float*)d_in[12];
    const float* Wd1 = (const float*)d_in[13];
    const float* bd1 = (const float*)d_in[14];
    const float* Wd2 = (const float*)d_in[15];
    const float* bd2 = (const float*)d_in[16];
    const float* Wd3 = (const float*)d_in[17];
    const float* bd3 = (const float*)d_in[18];
    float* out = (float*)d_out;

    float *p_y1, *p_h1, *p_y2;
    cudaGetSymbolAddress((void**)&p_y1, g_y1);
    cudaGetSymbolAddress((void**)&p_h1, g_h1);
    cudaGetSymbolAddress((void**)&p_y2, g_y2);

    zero_kernel<<<1184, 256>>>();

    // GEMM1: y1 = x @ [W1l | W1r]   (M=50000, K=512, N=256)
    {
        dim3 grid(2, (N_NODES + 127) / 128);
        sgemm_dualw<128, 128, 16, 8, 8, 128><<<grid, 256>>>(x, W1l, W1r, p_y1, N_NODES, 512);
    }

    edge_agg1<<<50000, 256>>>(ei);         // 8 edges/block (warp per edge)
    epi1<<<N_NODES, 128>>>(b1l);

    // GEMM2: y2 = h1 @ [W2l | W2r]  (M=50000, K=128, N=64)
    {
        dim3 grid(1, (N_NODES + 127) / 128);
        sgemm_dualw<128, 64, 16, 8, 4, 32><<<grid, 256>>>(p_h1, W2l, W2r, p_y2, N_NODES, 128);
    }

    edge_agg2<<<12500, 256>>>(ei);         // 32 edges/block (8 threads per edge)

    {
        dim3 blk(32, 8);
        pool_kernel<<<(N_NODES + 511) / 512, blk>>>(bat, b2l);
    }

    mlp_kernel<<<1, 64>>>(Wl1, bl1, Wl2, bl2, Wd1, bd1, Wd2, bd2, Wd3, bd3, out);
}

// round 4
// speedup vs baseline: 1.5881x; 1.5881x over previous
#include <cuda_runtime.h>
#include <cuda_bf16.h>
#include <cstdint>

#define N_NODES  50000
#define N_EDGES  400000
#define N_GRAPHS 64

// ============================ device scratch ===============================
__device__ __nv_bfloat16 g_w1hi[256 * 512];  // [Wl|Wr]^T hi, [256 n][512 k]
__device__ __nv_bfloat16 g_w1lo[256 * 512];  // lo
__device__ float g_y1[N_NODES * 256];        // [x@W1l | x@W1r]
__device__ float g_agg1[N_NODES * 128];
__device__ float g_cnt[N_NODES];
__device__ float g_h1[N_NODES * 128];
__device__ float g_y2[N_NODES * 64];
__device__ float g_agg2[N_NODES * 32];
__device__ float g_gsum[N_GRAPHS * 32];
__device__ float g_gcnt[N_GRAPHS];

// ============================ zero accumulators ============================
__global__ void zero_kernel() {
    size_t i = (size_t)blockIdx.x * blockDim.x + threadIdx.x;
    size_t stride = (size_t)gridDim.x * blockDim.x;
    for (size_t k = i; k < (size_t)N_NODES * 128; k += stride) g_agg1[k] = 0.f;
    for (size_t k = i; k < (size_t)N_NODES * 32;  k += stride) g_agg2[k] = 0.f;
    for (size_t k = i; k < (size_t)N_NODES;       k += stride) g_cnt[k]  = 0.f;
    for (size_t k = i; k < (size_t)N_GRAPHS * 32; k += stride) g_gsum[k] = 0.f;
    for (size_t k = i; k < (size_t)N_GRAPHS;      k += stride) g_gcnt[k] = 0.f;
}

// ============ weight transpose + bf16 hi/lo split: [256 n][512 k] ==========
__global__ void convert_w(const float* __restrict__ Wl, const float* __restrict__ Wr) {
    int idx = blockIdx.x * blockDim.x + threadIdx.x;
    if (idx >= 256 * 512) return;
    int n = idx >> 9, k = idx & 511;
    float v = (n < 128) ? Wl[k * 128 + n] : Wr[k * 128 + (n - 128)];
    __nv_bfloat16 h = __float2bfloat16_rn(v);
    __nv_bfloat16 l = __float2bfloat16_rn(v - __bfloat162float(h));
    g_w1hi[idx] = h;
    g_w1lo[idx] = l;
}

// ================== GEMM1 via mma.sync bf16x3 (tensor pipe) =================
// y1[M,256] = x[M,512] @ W^T[256,512], with x,W split hi+lo bf16;
// acc = hi*hi + hi*lo + lo*hi (fp32 accumulate).
#define BKW 32
#define LDT 40            // padded row: 32 + 8 bf16 (80 B -> conflict-free, 16B aligned)

__device__ __forceinline__ void mma16816(float* c, const uint32_t* a, const uint32_t* b) {
    asm volatile(
        "mma.sync.aligned.m16n8k16.row.col.f32.bf16.bf16.f32 "
        "{%0,%1,%2,%3}, {%4,%5,%6,%7}, {%8,%9}, {%0,%1,%2,%3};"
        : "+f"(c[0]), "+f"(c[1]), "+f"(c[2]), "+f"(c[3])
        : "r"(a[0]), "r"(a[1]), "r"(a[2]), "r"(a[3]), "r"(b[0]), "r"(b[1]));
}
__device__ __forceinline__ uint32_t pack_bf2(__nv_bfloat16 a, __nv_bfloat16 b) {
    __nv_bfloat162 t = __halves2bfloat162(a, b);
    return *(uint32_t*)&t;
}

__global__ __launch_bounds__(256) void gemm1_mma(const float* __restrict__ x,
                                                 float* __restrict__ y1, int M) {
    __shared__ __nv_bfloat16 sAhi[128][LDT], sAlo[128][LDT];
    __shared__ __nv_bfloat16 sBhi[128][LDT], sBlo[128][LDT];

    const int tid  = threadIdx.x;
    const int lane = tid & 31, wid = tid >> 5;
    const int wm = (wid & 3) * 32;   // warp M offset in tile
    const int wn = (wid >> 2) * 64;  // warp N offset in tile
    const int rowBase = blockIdx.y * 128;
    const int colBase = blockIdx.x * 128;

    float acc[2][8][4];
#pragma unroll
    for (int i = 0; i < 2; i++)
#pragma unroll
        for (int j = 0; j < 8; j++)
#pragma unroll
            for (int q = 0; q < 4; q++) acc[i][j][q] = 0.f;

    const int g4  = lane & 3;        // (lane%4)
    const int gID = lane >> 2;       // lane/4

    for (int kt = 0; kt < 512; kt += BKW) {
        // ---- A tile: 128 rows x 32 k, fp32 -> bf16 hi/lo split in-register ----
        // 512 groups of 8 floats, 2 per thread.
#pragma unroll
        for (int p = 0; p < 2; p++) {
            int i = tid + p * 256;       // 0..511
            int row = i >> 2;
            int g = i & 3;               // k8-group
            int gr = rowBase + row;
            float4 v0 = make_float4(0.f, 0.f, 0.f, 0.f), v1 = v0;
            if (gr < M) {
                const float4* src = (const float4*)(x + (size_t)gr * 512 + kt + g * 8);
                v0 = src[0]; v1 = src[1];
            }
            float v[8] = {v0.x, v0.y, v0.z, v0.w, v1.x, v1.y, v1.z, v1.w};
            __nv_bfloat16 h[8], l[8];
#pragma unroll
            for (int j = 0; j < 8; j++) {
                h[j] = __float2bfloat16_rn(v[j]);
                l[j] = __float2bfloat16_rn(v[j] - __bfloat162float(h[j]));
            }
            *(uint4*)&sAhi[row][g * 8] = make_uint4(pack_bf2(h[0], h[1]), pack_bf2(h[2], h[3]),
                                                    pack_bf2(h[4], h[5]), pack_bf2(h[6], h[7]));
            *(uint4*)&sAlo[row][g * 8] = make_uint4(pack_bf2(l[0], l[1]), pack_bf2(l[2], l[3]),
                                                    pack_bf2(l[4], l[5]), pack_bf2(l[6], l[7]));
        }
        // ---- B tile: rows colBase..+127 of presplit weights ----
#pragma unroll
        for (int p = 0; p < 2; p++) {
            int i = tid + p * 256;
            int row = i >> 2;
            int g = i & 3;
            size_t gi = (size_t)(colBase + row) * 512 + kt + g * 8;
            *(uint4*)&sBhi[row][g * 8] = *(const uint4*)(g_w1hi + gi);
            *(uint4*)&sBlo[row][g * 8] = *(const uint4*)(g_w1lo + gi);
        }
        __syncthreads();

        // ---- 3 combinations: Ahi*Bhi, Ahi*Blo, Alo*Bhi ----
#pragma unroll
        for (int cmb = 0; cmb < 3; cmb++) {
            const __nv_bfloat16 (*A)[LDT] = (cmb == 2) ? sAlo : sAhi;
            const __nv_bfloat16 (*B)[LDT] = (cmb == 1) ? sBlo : sBhi;
#pragma unroll
            for (int kk = 0; kk < BKW; kk += 16) {
                uint32_t a[2][4];
#pragma unroll
                for (int mt = 0; mt < 2; mt++) {
                    int r = wm + mt * 16 + gID;
                    int c = kk + g4 * 2;
                    a[mt][0] = *(const uint32_t*)&A[r][c];
                    a[mt][1] = *(const uint32_t*)&A[r + 8][c];
                    a[mt][2] = *(const uint32_t*)&A[r][c + 8];
                    a[mt][3] = *(const uint32_t*)&A[r + 8][c + 8];
                }
#pragma unroll
                for (int nt = 0; nt < 8; nt++) {
                    int n = wn + nt * 8 + gID;
                    int c = kk + g4 * 2;
                    uint32_t b[2];
                    b[0] = *(const uint32_t*)&B[n][c];
                    b[1] = *(const uint32_t*)&B[n][c + 8];
                    mma16816(acc[0][nt], a[0], b);
                    mma16816(acc[1][nt], a[1], b);
                }
            }
        }
        __syncthreads();
    }

    // ---- epilogue: fp32 accumulators -> y1 ----
#pragma unroll
    for (int mt = 0; mt < 2; mt++) {
        int r0 = rowBase + wm + mt * 16 + gID;
#pragma unroll
        for (int nt = 0; nt < 8; nt++) {
            int cc = colBase + wn + nt * 8 + g4 * 2;
            if (r0 < M)
                *(float2*)(y1 + (size_t)r0 * 256 + cc) = make_float2(acc[mt][nt][0], acc[mt][nt][1]);
            if (r0 + 8 < M)
                *(float2*)(y1 + (size_t)(r0 + 8) * 256 + cc) = make_float2(acc[mt][nt][2], acc[mt][nt][3]);
        }
    }
}

// ---------------- generic fp32 GEMM, C = A @ [Wl | Wr] (GEMM2) -------------
template<int BM, int BN, int BK, int TM, int TN, int HALFN>
__launch_bounds__(256)
__global__ void sgemm_dualw(const float* __restrict__ A,
                            const float* __restrict__ Wl,
                            const float* __restrict__ Wr,
                            float* __restrict__ C, int M, int K)
{
    constexpr int N = 2 * HALFN;
    __shared__ float As[BK][BM];
    __shared__ float Bs[BK][BN];

    const int tid = threadIdx.x;
    const int rowBase = blockIdx.y * BM;
    const int colBase = blockIdx.x * BN;

    constexpr int TX = BN / TN;
    const int tx = tid % TX;
    const int ty = tid / TX;

    float acc[TM][TN];
#pragma unroll
    for (int i = 0; i < TM; i++)
#pragma unroll
        for (int j = 0; j < TN; j++) acc[i][j] = 0.f;

    constexpr int AKT = BK / 4;
    constexpr int AROWS = 256 / AKT;
    constexpr int APASS = BM / AROWS;
    const int aRow = tid / AKT;
    const int aK4  = (tid % AKT) * 4;

    constexpr int BNT = BN / 4;
    constexpr int BKP = 256 / BNT;
    constexpr int BPASS = BK / BKP;
    const int bK  = tid / BNT;
    const int bN4 = (tid % BNT) * 4;

    for (int kt = 0; kt < K; kt += BK) {
#pragma unroll
        for (int p = 0; p < APASS; p++) {
            int r = aRow + p * AROWS;
            int gr = rowBase + r;
            float4 v = make_float4(0.f, 0.f, 0.f, 0.f);
            if (gr < M) v = *(const float4*)(A + (size_t)gr * K + kt + aK4);
            As[aK4 + 0][r] = v.x; As[aK4 + 1][r] = v.y;
            As[aK4 + 2][r] = v.z; As[aK4 + 3][r] = v.w;
        }
#pragma unroll
        for (int p = 0; p < BPASS; p++) {
            int k = bK + p * BKP;
            int gn = colBase + bN4;
            const float* src = (gn < HALFN)
                ? (Wl + (size_t)(kt + k) * HALFN + gn)
                : (Wr + (size_t)(kt + k) * HALFN + (gn - HALFN));
            *(float4*)&Bs[k][bN4] = *(const float4*)src;
        }
        __syncthreads();

#pragma unroll
        for (int kk = 0; kk < BK; kk++) {
            float a[TM], b[TN];
#pragma unroll
            for (int i = 0; i < TM; i++) a[i] = As[kk][ty * TM + i];
#pragma unroll
            for (int j = 0; j < TN; j++) b[j] = Bs[kk][tx * TN + j];
#pragma unroll
            for (int i = 0; i < TM; i++)
#pragma unroll
                for (int j = 0; j < TN; j++)
                    acc[i][j] = fmaf(a[i], b[j], acc[i][j]);
        }
        __syncthreads();
    }

#pragma unroll
    for (int i = 0; i < TM; i++) {
        int gr = rowBase + ty * TM + i;
        if (gr < M) {
#pragma unroll
            for (int j = 0; j < TN; j += 4) {
                float4 v = make_float4(acc[i][j], acc[i][j + 1], acc[i][j + 2], acc[i][j + 3]);
                *(float4*)(C + (size_t)gr * N + colBase + tx * TN + j) = v;
            }
        }
    }
}

// ---------------- edge aggregation, layer 1 (128 feats, warp per edge) -----
__global__ void edge_agg1(const int* __restrict__ ei) {
    int gtid = blockIdx.x * blockDim.x + threadIdx.x;
    int e = gtid >> 5;
    int lane = gtid & 31;
    if (e >= N_EDGES) return;
    int src = ei[e];
    int dst = ei[N_EDGES + e];
    float4 v = *(const float4*)(g_y1 + (size_t)src * 256 + lane * 4);
    float* p = g_agg1 + (size_t)dst * 128 + lane * 4;
    asm volatile("red.global.add.v4.f32 [%0], {%1,%2,%3,%4};"
                 :: "l"(p), "f"(v.x), "f"(v.y), "f"(v.z), "f"(v.w) : "memory");
    if (lane == 0) atomicAdd(&g_cnt[dst], 1.0f);
}

// ---------------- layer-1 epilogue: h1 = relu(agg/cnt + b1l + y1r) ---------
__global__ void epi1(const float* __restrict__ b1l) {
    int idx = blockIdx.x * blockDim.x + threadIdx.x;   // over N_NODES*32 float4s
    if (idx >= N_NODES * 32) return;
    int m = idx >> 5, q = idx & 31;
    float inv = 1.0f / fmaxf(g_cnt[m], 1.0f);
    float4 a = ((const float4*)g_agg1)[idx];
    float4 r = ((const float4*)g_y1)[(size_t)m * 64 + 32 + q];
    float4 b = ((const float4*)b1l)[q];
    float4 o;
    o.x = fmaxf(a.x * inv + b.x + r.x, 0.f);
    o.y = fmaxf(a.y * inv + b.y + r.y, 0.f);
    o.z = fmaxf(a.z * inv + b.z + r.z, 0.f);
    o.w = fmaxf(a.w * inv + b.w + r.w, 0.f);
    ((float4*)g_h1)[idx] = o;
}

// ---------------- edge aggregation, layer 2 (32 feats, 8 threads/edge) -----
__global__ void edge_agg2(const int* __restrict__ ei) {
    int gtid = blockIdx.x * blockDim.x + threadIdx.x;
    int e = gtid >> 3;
    int lane = gtid & 7;
    if (e >= N_EDGES) return;
    int src = ei[e];
    int dst = ei[N_EDGES + e];
    float4 v = *(const float4*)(g_y2 + (size_t)src * 64 + lane * 4);
    float* p = g_agg2 + (size_t)dst * 32 + lane * 4;
    asm volatile("red.global.add.v4.f32 [%0], {%1,%2,%3,%4};"
                 :: "l"(p), "f"(v.x), "f"(v.y), "f"(v.z), "f"(v.w) : "memory");
}

// ---------------- fused layer-2 epilogue + per-graph mean pool --------------
__global__ void pool_kernel(const int* __restrict__ batch, const float* __restrict__ b2l) {
    int f = threadIdx.x;           // 32
    int yid = threadIdx.y;         // 8
    int n0 = blockIdx.x * 512 + yid;
    float b = b2l[f];
    float acc = 0.f, cacc = 0.f;
    int cur = -1;
    for (int it = 0; it < 64; it++) {
        int n = n0 + it * 8;
        if (n < N_NODES) {
            int g = batch[n];
            if (g != cur) {
                if (cur >= 0) {
                    atomicAdd(&g_gsum[cur * 32 + f], acc);
                    if (f == 0) atomicAdd(&g_gcnt[cur], cacc);
                }
                cur = g; acc = 0.f; cacc = 0.f;
            }
            float inv = 1.0f / fmaxf(g_cnt[n], 1.0f);
            float v = g_agg2[(size_t)n * 32 + f] * inv + b + g_y2[(size_t)n * 64 + 32 + f];
            acc += fmaxf(v, 0.f);
            cacc += 1.f;
        }
    }
    if (cur >= 0) {
        atomicAdd(&g_gsum[cur * 32 + f], acc);
        if (f == 0) atomicAdd(&g_gcnt[cur], cacc);
    }
}

// ---------------- final tiny MLP (encoder head + decoder) ------------------
__global__ void mlp_kernel(const float* __restrict__ Wl1, const float* __restrict__ bl1,
                           const float* __restrict__ Wl2, const float* __restrict__ bl2,
                           const float* __restrict__ Wd1, const float* __restrict__ bd1,
                           const float* __restrict__ Wd2, const float* __restrict__ bd2,
                           const float* __restrict__ Wd3, const float* __restrict__ bd3,
                           float* __restrict__ out) {
    __shared__ float sWl1[1024], sWl2[512], sWd1[512], sWd2[1024], sWd3[1600];
    __shared__ float sbl1[32], sbl2[16], sbd1[32], sbd2[32], sbd3[50];
    int t = threadIdx.x;           // 64
    for (int i = t; i < 1024; i += 64) sWl1[i] = Wl1[i];
    for (int i = t; i < 512;  i += 64) sWl2[i] = Wl2[i];
    for (int i = t; i < 512;  i += 64) sWd1[i] = Wd1[i];
    for (int i = t; i < 1024; i += 64) sWd2[i] = Wd2[i];
    for (int i = t; i < 1600; i += 64) sWd3[i] = Wd3[i];
    if (t < 32) sbl1[t] = bl1[t];
    if (t < 16) sbl2[t] = bl2[t];
    if (t < 32) sbd1[t] = bd1[t];
    if (t < 32) sbd2[t] = bd2[t];
    for (int i = t; i < 50; i += 64) sbd3[i] = bd3[i];
    __syncthreads();
    if (t >= N_GRAPHS) return;

    float gv[32];
    float inv = 1.0f / fmaxf(g_gcnt[t], 1.0f);
#pragma unroll
    for (int i = 0; i < 32; i++) gv[i] = g_gsum[t * 32 + i] * inv;

    float a[32];
#pragma unroll
    for (int j = 0; j < 32; j++) {
        float s = sbl1[j];
#pragma unroll
        for (int i = 0; i < 32; i++) s = fmaf(gv[i], sWl1[i * 32 + j], s);
        a[j] = fmaxf(s, 0.f);
    }
    float enc[16];
#pragma unroll
    for (int j = 0; j < 16; j++) {
        float s = sbl2[j];
#pragma unroll
        for (int i = 0; i < 32; i++) s = fmaf(a[i], sWl2[i * 16 + j], s);
        enc[j] = s > 0.f ? s : 0.1f * s;
    }
#pragma unroll
    for (int j = 0; j < 16; j++) out[t * 16 + j] = enc[j];

    float z1[32];
#pragma unroll
    for (int j = 0; j < 32; j++) {
        float s = sbd1[j];
#pragma unroll
        for (int i = 0; i < 16; i++) s = fmaf(enc[i], sWd1[i * 32 + j], s);
        z1[j] = s > 0.f ? s : 0.1f * s;
    }
    float z2[32];
#pragma unroll
    for (int j = 0; j < 32; j++) {
        float s = sbd2[j];
#pragma unroll
        for (int i = 0; i < 32; i++) s = fmaf(z1[i], sWd2[i * 32 + j], s);
        z2[j] = s > 0.f ? s : 0.1f * s;
    }
#pragma unroll
    for (int j = 0; j < 50; j++) {
        float s = sbd3[j];
#pragma unroll
        for (int i = 0; i < 32; i++) s = fmaf(z2[i], sWd3[i * 50 + j], s);
        out[1024 + t * 50 + j] = s;
    }
}

// ---------------- launch ----------------------------------------------------
extern "C" void kernel_launch(void* const* d_in, const int* in_sizes, int n_in,
                              void* d_out, int out_size) {
    const float* x   = (const float*)d_in[0];
    const int*   ei  = (const int*)d_in[1];
    const int*   bat = (const int*)d_in[2];
    const float* W1l = (const float*)d_in[3];
    const float* b1l = (const float*)d_in[4];
    const float* W1r = (const float*)d_in[5];
    const float* W2l = (const float*)d_in[6];
    const float* b2l = (const float*)d_in[7];
    const float* W2r = (const float*)d_in[8];
    const float* Wl1 = (const float*)d_in[9];
    const float* bl1 = (const float*)d_in[10];
    const float* Wl2 = (const float*)d_in[11];
    const float* bl2 = (const float*)d_in[12];
    const float* Wd1 = (const float*)d_in[13];
    const float* bd1 = (const float*)d_in[14];
    const float* Wd2 = (const float*)d_in[15];
    const float* bd2 = (const float*)d_in[16];
    const float* Wd3 = (const float*)d_in[17];
    const float* bd3 = (const float*)d_in[18];
    float* out = (float*)d_out;

    float *p_y1, *p_h1, *p_y2;
    cudaGetSymbolAddress((void**)&p_y1, g_y1);
    cudaGetSymbolAddress((void**)&p_h1, g_h1);
    cudaGetSymbolAddress((void**)&p_y2, g_y2);

    zero_kernel<<<1184, 256>>>();
    convert_w<<<512, 256>>>(W1l, W1r);

    // GEMM1 on tensor pipe: y1 = x @ [W1l | W1r]  (M=50000, K=512, N=256)
    {
        dim3 grid(2, (N_NODES + 127) / 128);
        gemm1_mma<<<grid, 256>>>(x, p_y1, N_NODES);
    }

    edge_agg1<<<50000, 256>>>(ei);
    epi1<<<(N_NODES * 32 + 255) / 256, 256>>>(b1l);

    // GEMM2: y2 = h1 @ [W2l | W2r]  (M=50000, K=128, N=64)
    {
        dim3 grid(1, (N_NODES + 127) / 128);
        sgemm_dualw<128, 64, 16, 8, 4, 32><<<grid, 256>>>(p_h1, W2l, W2r, p_y2, N_NODES, 128);
    }

    edge_agg2<<<12500, 256>>>(ei);

    {
        dim3 blk(32, 8);
        pool_kernel<<<(N_NODES + 511) / 512, blk>>>(bat, b2l);
    }

    mlp_kernel<<<1, 64>>>(Wl1, bl1, Wl2, bl2, Wd1, bd1, Wd2, bd2, Wd3, bd3, out);
}